// round 6
// baseline (speedup 1.0000x reference)
#include <cuda_runtime.h>
#include <cuda_bf16.h>
#include <stdint.h>
#include <math.h>

// ---------------- problem constants ----------------
#define T_TOKENS 8192          // 4 * 2048
#define DD 1024                // emb dim
#define HH 4096                // hidden dim
#define EE 8                   // experts
#define PAIRS (T_TOKENS * 2)   // 16384 routed (token, expert) pairs

// ---------------- device scratch (static; no allocation allowed) ----------------
__device__ int   g_count[EE];
__device__ int   g_offset[EE];
__device__ int   g_ek[PAIRS];
__device__ int   g_slot[PAIRS];
__device__ float g_gate[PAIRS];
__device__ int   g_row[PAIRS];
__device__ int   g_tok[PAIRS];
__device__ float g_hid[(size_t)PAIRS * HH];     // 268 MB (tf32-rounded at write)
__device__ float g_y  [(size_t)PAIRS * DD];     // 67 MB
__device__ float g_xr [(size_t)T_TOKENS * DD];  // 33 MB tf32-rounded x
__device__ float g_w1r[(size_t)EE * DD * HH];   // 134 MB tf32-rounded w1
__device__ float g_w2r[(size_t)EE * HH * DD];   // 134 MB tf32-rounded w2

// ---------------- helpers ----------------
__device__ __forceinline__ uint32_t smem_u32(const void* p) {
    uint32_t a;
    asm("{ .reg .u64 t; cvta.to.shared.u64 t, %1; cvt.u32.u64 %0, t; }" : "=r"(a) : "l"(p));
    return a;
}
__device__ __forceinline__ void cp_async16(uint32_t dst, const void* src) {
    asm volatile("cp.async.cg.shared.global [%0], [%1], 16;" :: "r"(dst), "l"(src));
}
__device__ __forceinline__ void cp_commit() {
    asm volatile("cp.async.commit_group;" ::: "memory");
}
template <int N>
__device__ __forceinline__ void cp_wait() {
    asm volatile("cp.async.wait_group %0;" :: "n"(N) : "memory");
}
__device__ __forceinline__ float f2tf(float v) {
    uint32_t r;
    asm("cvt.rna.tf32.f32 %0, %1;" : "=r"(r) : "f"(v));
    return __uint_as_float(r);
}
__device__ __forceinline__ void mma_tf32(float* d, const uint32_t* a, const uint32_t* b) {
    asm volatile(
        "mma.sync.aligned.m16n8k8.row.col.f32.tf32.tf32.f32 "
        "{%0,%1,%2,%3}, {%4,%5,%6,%7}, {%8,%9}, {%0,%1,%2,%3};"
        : "+f"(d[0]), "+f"(d[1]), "+f"(d[2]), "+f"(d[3])
        : "r"(a[0]), "r"(a[1]), "r"(a[2]), "r"(a[3]), "r"(b[0]), "r"(b[1]));
}

// ---------------- kernel: elementwise tf32 pre-round ----------------
__global__ void round_tf32_kernel(const float4* __restrict__ src,
                                  float4* __restrict__ dst, int n4) {
    int i = blockIdx.x * blockDim.x + threadIdx.x;
    int stride = gridDim.x * blockDim.x;
    for (; i < n4; i += stride) {
        float4 v = src[i];
        v.x = f2tf(v.x); v.y = f2tf(v.y); v.z = f2tf(v.z); v.w = f2tf(v.w);
        dst[i] = v;
    }
}

// ---------------- kernel 0: zero counters ----------------
__global__ void zero_counts_kernel() {
    if (threadIdx.x < EE) g_count[threadIdx.x] = 0;
}

// ---------------- kernel 1: router (1 warp per token, fp32) ----------------
__global__ void router_kernel(const float* __restrict__ x,
                              const float* __restrict__ wr,
                              const float* __restrict__ br) {
    int warp = (blockIdx.x * blockDim.x + threadIdx.x) >> 5;
    int lane = threadIdx.x & 31;
    if (warp >= T_TOKENS) return;
    const float* xr = x + (size_t)warp * DD;

    float acc[EE];
#pragma unroll
    for (int e = 0; e < EE; e++) acc[e] = 0.f;
#pragma unroll 4
    for (int c = 0; c < DD / 32; c++) {
        int k = c * 32 + lane;
        float xv = __ldg(xr + k);
        const float4* w4 = reinterpret_cast<const float4*>(wr + (size_t)k * EE);
        float4 a = __ldg(&w4[0]);
        float4 b = __ldg(&w4[1]);
        acc[0] += xv * a.x; acc[1] += xv * a.y; acc[2] += xv * a.z; acc[3] += xv * a.w;
        acc[4] += xv * b.x; acc[5] += xv * b.y; acc[6] += xv * b.z; acc[7] += xv * b.w;
    }
#pragma unroll
    for (int e = 0; e < EE; e++)
#pragma unroll
        for (int o = 16; o > 0; o >>= 1)
            acc[e] += __shfl_down_sync(0xffffffffu, acc[e], o);

    if (lane == 0) {
        float l[EE];
        float mx = -1e30f;
#pragma unroll
        for (int e = 0; e < EE; e++) { l[e] = acc[e] + br[e]; mx = fmaxf(mx, l[e]); }
        float s = 0.f;
#pragma unroll
        for (int e = 0; e < EE; e++) { l[e] = expf(l[e] - mx); s += l[e]; }
        float inv = 1.0f / s;
        int e0 = 0;
#pragma unroll
        for (int e = 1; e < EE; e++) if (l[e] > l[e0]) e0 = e;
        int e1 = (e0 == 0) ? 1 : 0;
#pragma unroll
        for (int e = 0; e < EE; e++) if (e != e0 && l[e] > l[e1]) e1 = e;
        int t = warp;
        int s0 = atomicAdd(&g_count[e0], 1);
        g_ek[t * 2 + 0] = e0; g_slot[t * 2 + 0] = s0; g_gate[t * 2 + 0] = l[e0] * inv;
        int s1 = atomicAdd(&g_count[e1], 1);
        g_ek[t * 2 + 1] = e1; g_slot[t * 2 + 1] = s1; g_gate[t * 2 + 1] = l[e1] * inv;
    }
}

// ---------------- kernel 2: prefix offsets ----------------
__global__ void offsets_kernel() {
    if (threadIdx.x == 0 && blockIdx.x == 0) {
        int s = 0;
#pragma unroll
        for (int e = 0; e < EE; e++) { g_offset[e] = s; s += g_count[e]; }
    }
}

// ---------------- kernel 3: scatter compact rows ----------------
__global__ void scatter_kernel() {
    int i = blockIdx.x * blockDim.x + threadIdx.x;
    if (i >= PAIRS) return;
    int e = g_ek[i];
    int row = g_offset[e] + g_slot[i];
    g_row[i] = row;
    g_tok[row] = i >> 1;
}

// ---------------- grouped GEMM via mma.sync tf32 (R3 shape, no inner CVT) ----
// C[m][n] = sum_k A[m][k] * W[k][n]  (+bias; FFN1 adds relu + tf32-round)
// Operands pre-rounded to tf32 -> fragments load as raw uint32_t.
// PROVEN register shape: 64 acc, 24 frag, launch_bounds(256,2) -> <=128 regs.
constexpr int BM = 128, BN = 128, BK = 32;
constexpr int A_STRIDE = BK + 4;             // 36 floats
constexpr int B_STRIDE = BN + 8;             // 136 floats
constexpr int A_TILE_F = BM * A_STRIDE;      // 4608 floats
constexpr int B_TILE_F = BK * B_STRIDE;      // 4352 floats
constexpr int STAGE_F  = A_TILE_F + B_TILE_F;
constexpr int GEMM_SMEM = 2 * STAGE_F * 4;   // 71680 bytes

template <int NN, int KK, bool FFN1>
__global__ void __launch_bounds__(256, 2)
moe_gemm_mma(const float* __restrict__ A_src,   // g_xr for FFN1, unused for FFN2
             const float* __restrict__ W_all,
             const float* __restrict__ bias_all) {
    constexpr int NCH = KK / BK;
    extern __shared__ float sm[];

    int e = blockIdx.z;
    int cnt = g_count[e];
    int m0 = blockIdx.y * BM;
    if (m0 >= cnt) return;
    int off = g_offset[e];
    int n0 = blockIdx.x * BN;

    const float* W    = W_all + (size_t)e * KK * NN;
    const float* bias = bias_all + (size_t)e * NN;
    float* C          = FFN1 ? g_hid : g_y;

    int tid = threadIdx.x;
    int wid = tid >> 5, lane = tid & 31;
    int wm = wid >> 2, wn = wid & 3;        // 2 x 4 warps; warp tile 64(m) x 32(n)
    int g = lane >> 2, tg = lane & 3;

    uint32_t sb = smem_u32(sm);

    // ---- per-thread load descriptors (R3 layout) ----
    const float* asrc[4];
    uint32_t adst[4];
    int aseg = tid & 7;
#pragma unroll
    for (int i = 0; i < 4; i++) {
        int r = i * 32 + (tid >> 3);
        int gm = m0 + r;
        if (gm > cnt - 1) gm = cnt - 1;     // clamp; masked in epilogue
        int grow = off + gm;
        const float* base = FFN1 ? (A_src + (size_t)g_tok[grow] * KK)
                                 : (g_hid + (size_t)grow * KK);
        asrc[i] = base + aseg * 4;
        adst[i] = sb + (uint32_t)(r * A_STRIDE + aseg * 4) * 4;
    }
    const float* bsrc[4];
    uint32_t bdst[4];
    int bseg = tid & 31;
#pragma unroll
    for (int i = 0; i < 4; i++) {
        int kr = i * 8 + (tid >> 5);
        bsrc[i] = W + (size_t)kr * NN + n0 + bseg * 4;
        bdst[i] = sb + (uint32_t)(A_TILE_F + kr * B_STRIDE + bseg * 4) * 4;
    }
    constexpr uint32_t STAGE_B = STAGE_F * 4;

    float acc[4][4][4];
#pragma unroll
    for (int mi = 0; mi < 4; mi++)
#pragma unroll
        for (int ni = 0; ni < 4; ni++)
#pragma unroll
            for (int q = 0; q < 4; q++) acc[mi][ni][q] = 0.f;

    // ---- prologue: stage 0 ----
#pragma unroll
    for (int i = 0; i < 4; i++) cp_async16(adst[i], asrc[i]);
#pragma unroll
    for (int i = 0; i < 4; i++) cp_async16(bdst[i], bsrc[i]);
    cp_commit();

#pragma unroll 1
    for (int c = 0; c < NCH; c++) {
        if (c + 1 < NCH) {
            int k0 = (c + 1) * BK;
            uint32_t so = ((c + 1) & 1) * STAGE_B;
#pragma unroll
            for (int i = 0; i < 4; i++) cp_async16(adst[i] + so, asrc[i] + k0);
#pragma unroll
            for (int i = 0; i < 4; i++)
                cp_async16(bdst[i] + so, bsrc[i] + (size_t)k0 * NN);
            cp_commit();
            cp_wait<1>();
        } else {
            cp_wait<0>();
        }
        __syncthreads();

        const uint32_t* As = reinterpret_cast<const uint32_t*>(sm) + (c & 1) * STAGE_F;
        const uint32_t* Bs = As + A_TILE_F;

#pragma unroll
        for (int kk = 0; kk < BK; kk += 8) {
            uint32_t af[4][4], bf[4][2];
#pragma unroll
            for (int mi = 0; mi < 4; mi++) {
                const uint32_t* ap = As + (wm * 64 + mi * 16 + g) * A_STRIDE + kk + tg;
                af[mi][0] = ap[0];
                af[mi][1] = ap[8 * A_STRIDE];
                af[mi][2] = ap[4];
                af[mi][3] = ap[8 * A_STRIDE + 4];
            }
#pragma unroll
            for (int ni = 0; ni < 4; ni++) {
                const uint32_t* bp = Bs + (kk + tg) * B_STRIDE + wn * 32 + ni * 8 + g;
                bf[ni][0] = bp[0];
                bf[ni][1] = bp[4 * B_STRIDE];
            }
#pragma unroll
            for (int mi = 0; mi < 4; mi++)
#pragma unroll
                for (int ni = 0; ni < 4; ni++)
                    mma_tf32(acc[mi][ni], af[mi], bf[ni]);
        }
        __syncthreads();
    }

    // ---- epilogue: bias (+relu + tf32 round for FFN1), masked float2 stores ----
#pragma unroll
    for (int mi = 0; mi < 4; mi++) {
        int r0 = m0 + wm * 64 + mi * 16 + g;
        int r1 = r0 + 8;
        bool v0 = r0 < cnt, v1 = r1 < cnt;
        float* p0 = C + (size_t)(off + r0) * NN + n0 + wn * 32;
        float* p1 = C + (size_t)(off + r1) * NN + n0 + wn * 32;
#pragma unroll
        for (int ni = 0; ni < 4; ni++) {
            int col = ni * 8 + 2 * tg;
            float2 bv = *reinterpret_cast<const float2*>(bias + n0 + wn * 32 + col);
            float2 o0, o1;
            o0.x = acc[mi][ni][0] + bv.x;
            o0.y = acc[mi][ni][1] + bv.y;
            o1.x = acc[mi][ni][2] + bv.x;
            o1.y = acc[mi][ni][3] + bv.y;
            if (FFN1) {
                o0.x = f2tf(fmaxf(o0.x, 0.f)); o0.y = f2tf(fmaxf(o0.y, 0.f));
                o1.x = f2tf(fmaxf(o1.x, 0.f)); o1.y = f2tf(fmaxf(o1.y, 0.f));
            }
            if (v0) *reinterpret_cast<float2*>(p0 + col) = o0;
            if (v1) *reinterpret_cast<float2*>(p1 + col) = o1;
        }
    }
}

// ---------------- combine pairs into output ----------------
__global__ void combine_kernel(float* __restrict__ out) {
    int i = blockIdx.x * blockDim.x + threadIdx.x;
    if (i >= T_TOKENS * (DD / 4)) return;
    int t  = i / (DD / 4);
    int d4 = i % (DD / 4);
    int r0 = g_row[t * 2 + 0];
    int r1 = g_row[t * 2 + 1];
    float g0 = g_gate[t * 2 + 0];
    float g1 = g_gate[t * 2 + 1];
    const float4* y0 = reinterpret_cast<const float4*>(g_y + (size_t)r0 * DD);
    const float4* y1 = reinterpret_cast<const float4*>(g_y + (size_t)r1 * DD);
    float4 a = y0[d4], b = y1[d4], o;
    o.x = g0 * a.x + g1 * b.x;
    o.y = g0 * a.y + g1 * b.y;
    o.z = g0 * a.z + g1 * b.z;
    o.w = g0 * a.w + g1 * b.w;
    reinterpret_cast<float4*>(out)[i] = o;
}

// ---------------- launch ----------------
extern "C" void kernel_launch(void* const* d_in, const int* in_sizes, int n_in,
                              void* d_out, int out_size) {
    const float* x  = (const float*)d_in[0];
    const float* wr = (const float*)d_in[1];
    const float* br = (const float*)d_in[2];
    const float* w1 = (const float*)d_in[3];
    const float* b1 = (const float*)d_in[4];
    const float* w2 = (const float*)d_in[5];
    const float* b2 = (const float*)d_in[6];
    float* out = (float*)d_out;

    cudaFuncSetAttribute(moe_gemm_mma<HH, DD, true>,
                         cudaFuncAttributeMaxDynamicSharedMemorySize, GEMM_SMEM);
    cudaFuncSetAttribute(moe_gemm_mma<DD, HH, false>,
                         cudaFuncAttributeMaxDynamicSharedMemorySize, GEMM_SMEM);

    // one-time operand pre-round to tf32 (removes all cvt from GEMM inner loops)
    round_tf32_kernel<<<2048, 256>>>((const float4*)x,  (float4*)g_xr,
                                     T_TOKENS * DD / 4);
    round_tf32_kernel<<<4096, 256>>>((const float4*)w1, (float4*)g_w1r,
                                     EE * DD * HH / 4);
    round_tf32_kernel<<<4096, 256>>>((const float4*)w2, (float4*)g_w2r,
                                     EE * HH * DD / 4);

    zero_counts_kernel<<<1, 32>>>();
    router_kernel<<<T_TOKENS / 8, 256>>>(x, wr, br);
    offsets_kernel<<<1, 32>>>();
    scatter_kernel<<<PAIRS / 256, 256>>>();

    // FFN1: N=4096, K=1024
    {
        dim3 grid(HH / BN, 8192 / BM, EE);
        moe_gemm_mma<HH, DD, true><<<grid, 256, GEMM_SMEM>>>(g_xr, g_w1r, b1);
    }
    // FFN2: N=1024, K=4096
    {
        dim3 grid(DD / BN, 8192 / BM, EE);
        moe_gemm_mma<DD, HH, false><<<grid, 256, GEMM_SMEM>>>(nullptr, g_w2r, b2);
    }

    combine_kernel<<<(T_TOKENS * (DD / 4)) / 256, 256>>>(out);
}

// round 7
// speedup vs baseline: 2.2612x; 2.2612x over previous
#include <cuda_runtime.h>
#include <cuda_bf16.h>
#include <stdint.h>
#include <math.h>

// ---------------- problem constants ----------------
#define T_TOKENS 8192          // 4 * 2048
#define DD 1024                // emb dim
#define HH 4096                // hidden dim
#define EE 8                   // experts
#define PAIRS (T_TOKENS * 2)   // 16384 routed (token, expert) pairs

// ---------------- device scratch (keep total ~R3 level; NO weight copies!) ----
__device__ int   g_count[EE];
__device__ int   g_offset[EE];
__device__ int   g_ek[PAIRS];
__device__ int   g_slot[PAIRS];
__device__ float g_gate[PAIRS];
__device__ int   g_row[PAIRS];
__device__ int   g_tok[PAIRS];
__device__ float g_hid[(size_t)PAIRS * HH];     // 268 MB (tf32-rounded at write)
__device__ float g_y  [(size_t)PAIRS * DD];     // 67 MB
__device__ float g_xr [(size_t)T_TOKENS * DD];  // 33 MB tf32-rounded x (A-side only)

// ---------------- helpers ----------------
__device__ __forceinline__ uint32_t smem_u32(const void* p) {
    uint32_t a;
    asm("{ .reg .u64 t; cvta.to.shared.u64 t, %1; cvt.u32.u64 %0, t; }" : "=r"(a) : "l"(p));
    return a;
}
__device__ __forceinline__ void cp_async16(uint32_t dst, const void* src) {
    asm volatile("cp.async.cg.shared.global [%0], [%1], 16;" :: "r"(dst), "l"(src));
}
__device__ __forceinline__ void cp_commit() {
    asm volatile("cp.async.commit_group;" ::: "memory");
}
template <int N>
__device__ __forceinline__ void cp_wait() {
    asm volatile("cp.async.wait_group %0;" :: "n"(N) : "memory");
}
__device__ __forceinline__ float f2tf(float v) {
    uint32_t r;
    asm("cvt.rna.tf32.f32 %0, %1;" : "=r"(r) : "f"(v));
    return __uint_as_float(r);
}
__device__ __forceinline__ uint32_t f2tf_u(float v) {
    uint32_t r;
    asm("cvt.rna.tf32.f32 %0, %1;" : "=r"(r) : "f"(v));
    return r;
}
__device__ __forceinline__ void mma_tf32(float* d, const uint32_t* a, const uint32_t* b) {
    asm volatile(
        "mma.sync.aligned.m16n8k8.row.col.f32.tf32.tf32.f32 "
        "{%0,%1,%2,%3}, {%4,%5,%6,%7}, {%8,%9}, {%0,%1,%2,%3};"
        : "+f"(d[0]), "+f"(d[1]), "+f"(d[2]), "+f"(d[3])
        : "r"(a[0]), "r"(a[1]), "r"(a[2]), "r"(a[3]), "r"(b[0]), "r"(b[1]));
}

// ---------------- kernel: tf32 pre-round (x only, 33 MB) ----------------
__global__ void round_x_kernel(const float4* __restrict__ src,
                               float4* __restrict__ dst, int n4) {
    int i = blockIdx.x * blockDim.x + threadIdx.x;
    int stride = gridDim.x * blockDim.x;
    for (; i < n4; i += stride) {
        float4 v = src[i];
        v.x = f2tf(v.x); v.y = f2tf(v.y); v.z = f2tf(v.z); v.w = f2tf(v.w);
        dst[i] = v;
    }
}

// ---------------- kernel 0: zero counters ----------------
__global__ void zero_counts_kernel() {
    if (threadIdx.x < EE) g_count[threadIdx.x] = 0;
}

// ---------------- kernel 1: router (1 warp per token, fp32, ORIGINAL x) ------
__global__ void router_kernel(const float* __restrict__ x,
                              const float* __restrict__ wr,
                              const float* __restrict__ br) {
    int warp = (blockIdx.x * blockDim.x + threadIdx.x) >> 5;
    int lane = threadIdx.x & 31;
    if (warp >= T_TOKENS) return;
    const float* xr = x + (size_t)warp * DD;

    float acc[EE];
#pragma unroll
    for (int e = 0; e < EE; e++) acc[e] = 0.f;
#pragma unroll 4
    for (int c = 0; c < DD / 32; c++) {
        int k = c * 32 + lane;
        float xv = __ldg(xr + k);
        const float4* w4 = reinterpret_cast<const float4*>(wr + (size_t)k * EE);
        float4 a = __ldg(&w4[0]);
        float4 b = __ldg(&w4[1]);
        acc[0] += xv * a.x; acc[1] += xv * a.y; acc[2] += xv * a.z; acc[3] += xv * a.w;
        acc[4] += xv * b.x; acc[5] += xv * b.y; acc[6] += xv * b.z; acc[7] += xv * b.w;
    }
#pragma unroll
    for (int e = 0; e < EE; e++)
#pragma unroll
        for (int o = 16; o > 0; o >>= 1)
            acc[e] += __shfl_down_sync(0xffffffffu, acc[e], o);

    if (lane == 0) {
        float l[EE];
        float mx = -1e30f;
#pragma unroll
        for (int e = 0; e < EE; e++) { l[e] = acc[e] + br[e]; mx = fmaxf(mx, l[e]); }
        float s = 0.f;
#pragma unroll
        for (int e = 0; e < EE; e++) { l[e] = expf(l[e] - mx); s += l[e]; }
        float inv = 1.0f / s;
        int e0 = 0;
#pragma unroll
        for (int e = 1; e < EE; e++) if (l[e] > l[e0]) e0 = e;
        int e1 = (e0 == 0) ? 1 : 0;
#pragma unroll
        for (int e = 0; e < EE; e++) if (e != e0 && l[e] > l[e1]) e1 = e;
        int t = warp;
        int s0 = atomicAdd(&g_count[e0], 1);
        g_ek[t * 2 + 0] = e0; g_slot[t * 2 + 0] = s0; g_gate[t * 2 + 0] = l[e0] * inv;
        int s1 = atomicAdd(&g_count[e1], 1);
        g_ek[t * 2 + 1] = e1; g_slot[t * 2 + 1] = s1; g_gate[t * 2 + 1] = l[e1] * inv;
    }
}

// ---------------- kernel 2: prefix offsets ----------------
__global__ void offsets_kernel() {
    if (threadIdx.x == 0 && blockIdx.x == 0) {
        int s = 0;
#pragma unroll
        for (int e = 0; e < EE; e++) { g_offset[e] = s; s += g_count[e]; }
    }
}

// ---------------- kernel 3: scatter compact rows ----------------
__global__ void scatter_kernel() {
    int i = blockIdx.x * blockDim.x + threadIdx.x;
    if (i >= PAIRS) return;
    int e = g_ek[i];
    int row = g_offset[e] + g_slot[i];
    g_row[i] = row;
    g_tok[row] = i >> 1;
}

// ---------------- grouped GEMM via mma.sync tf32 (R3 shape) ----------------
// C[m][n] = sum_k A[m][k] * W[k][n]  (+bias; FFN1 adds relu + tf32-round)
// A operands (g_xr / g_hid) are pre-rounded -> A fragments load raw (no cvt).
// B operands (w1/w2 from HARNESS buffers) keep in-loop cvt.
constexpr int BM = 128, BN = 128, BK = 32;
constexpr int A_STRIDE = BK + 4;             // 36 floats
constexpr int B_STRIDE = BN + 8;             // 136 floats
constexpr int A_TILE_F = BM * A_STRIDE;      // 4608 floats
constexpr int B_TILE_F = BK * B_STRIDE;      // 4352 floats
constexpr int STAGE_F  = A_TILE_F + B_TILE_F;
constexpr int GEMM_SMEM = 2 * STAGE_F * 4;   // 71680 bytes

template <int NN, int KK, bool FFN1>
__global__ void __launch_bounds__(256, 2)
moe_gemm_mma(const float* __restrict__ A_src,   // g_xr for FFN1, unused for FFN2
             const float* __restrict__ W_all,
             const float* __restrict__ bias_all) {
    constexpr int NCH = KK / BK;
    extern __shared__ float sm[];

    int e = blockIdx.z;
    int cnt = g_count[e];
    int m0 = blockIdx.y * BM;
    if (m0 >= cnt) return;
    int off = g_offset[e];
    int n0 = blockIdx.x * BN;

    const float* W    = W_all + (size_t)e * KK * NN;
    const float* bias = bias_all + (size_t)e * NN;
    float* C          = FFN1 ? g_hid : g_y;

    int tid = threadIdx.x;
    int wid = tid >> 5, lane = tid & 31;
    int wm = wid >> 2, wn = wid & 3;        // 2 x 4 warps; warp tile 64(m) x 32(n)
    int g = lane >> 2, tg = lane & 3;

    uint32_t sb = smem_u32(sm);

    // ---- per-thread load descriptors (R3 layout) ----
    const float* asrc[4];
    uint32_t adst[4];
    int aseg = tid & 7;
#pragma unroll
    for (int i = 0; i < 4; i++) {
        int r = i * 32 + (tid >> 3);
        int gm = m0 + r;
        if (gm > cnt - 1) gm = cnt - 1;     // clamp; masked in epilogue
        int grow = off + gm;
        const float* base = FFN1 ? (A_src + (size_t)g_tok[grow] * KK)
                                 : (g_hid + (size_t)grow * KK);
        asrc[i] = base + aseg * 4;
        adst[i] = sb + (uint32_t)(r * A_STRIDE + aseg * 4) * 4;
    }
    const float* bsrc[4];
    uint32_t bdst[4];
    int bseg = tid & 31;
#pragma unroll
    for (int i = 0; i < 4; i++) {
        int kr = i * 8 + (tid >> 5);
        bsrc[i] = W + (size_t)kr * NN + n0 + bseg * 4;
        bdst[i] = sb + (uint32_t)(A_TILE_F + kr * B_STRIDE + bseg * 4) * 4;
    }
    constexpr uint32_t STAGE_B = STAGE_F * 4;

    float acc[4][4][4];
#pragma unroll
    for (int mi = 0; mi < 4; mi++)
#pragma unroll
        for (int ni = 0; ni < 4; ni++)
#pragma unroll
            for (int q = 0; q < 4; q++) acc[mi][ni][q] = 0.f;

    // ---- prologue: stage 0 ----
#pragma unroll
    for (int i = 0; i < 4; i++) cp_async16(adst[i], asrc[i]);
#pragma unroll
    for (int i = 0; i < 4; i++) cp_async16(bdst[i], bsrc[i]);
    cp_commit();

#pragma unroll 1
    for (int c = 0; c < NCH; c++) {
        if (c + 1 < NCH) {
            int k0 = (c + 1) * BK;
            uint32_t so = ((c + 1) & 1) * STAGE_B;
#pragma unroll
            for (int i = 0; i < 4; i++) cp_async16(adst[i] + so, asrc[i] + k0);
#pragma unroll
            for (int i = 0; i < 4; i++)
                cp_async16(bdst[i] + so, bsrc[i] + (size_t)k0 * NN);
            cp_commit();
            cp_wait<1>();
        } else {
            cp_wait<0>();
        }
        __syncthreads();

        const uint32_t* As = reinterpret_cast<const uint32_t*>(sm) + (c & 1) * STAGE_F;
        const float*    Bs = sm + (c & 1) * STAGE_F + A_TILE_F;

#pragma unroll
        for (int kk = 0; kk < BK; kk += 8) {
            uint32_t af[4][4], bf[4][2];
#pragma unroll
            for (int mi = 0; mi < 4; mi++) {
                const uint32_t* ap = As + (wm * 64 + mi * 16 + g) * A_STRIDE + kk + tg;
                af[mi][0] = ap[0];                      // pre-rounded: raw load
                af[mi][1] = ap[8 * A_STRIDE];
                af[mi][2] = ap[4];
                af[mi][3] = ap[8 * A_STRIDE + 4];
            }
#pragma unroll
            for (int ni = 0; ni < 4; ni++) {
                const float* bp = Bs + (kk + tg) * B_STRIDE + wn * 32 + ni * 8 + g;
                bf[ni][0] = f2tf_u(bp[0]);              // raw weights: cvt here
                bf[ni][1] = f2tf_u(bp[4 * B_STRIDE]);
            }
#pragma unroll
            for (int mi = 0; mi < 4; mi++)
#pragma unroll
                for (int ni = 0; ni < 4; ni++)
                    mma_tf32(acc[mi][ni], af[mi], bf[ni]);
        }
        __syncthreads();
    }

    // ---- epilogue: bias (+relu + tf32 round for FFN1), masked float2 stores ----
#pragma unroll
    for (int mi = 0; mi < 4; mi++) {
        int r0 = m0 + wm * 64 + mi * 16 + g;
        int r1 = r0 + 8;
        bool v0 = r0 < cnt, v1 = r1 < cnt;
        float* p0 = C + (size_t)(off + r0) * NN + n0 + wn * 32;
        float* p1 = C + (size_t)(off + r1) * NN + n0 + wn * 32;
#pragma unroll
        for (int ni = 0; ni < 4; ni++) {
            int col = ni * 8 + 2 * tg;
            float2 bv = *reinterpret_cast<const float2*>(bias + n0 + wn * 32 + col);
            float2 o0, o1;
            o0.x = acc[mi][ni][0] + bv.x;
            o0.y = acc[mi][ni][1] + bv.y;
            o1.x = acc[mi][ni][2] + bv.x;
            o1.y = acc[mi][ni][3] + bv.y;
            if (FFN1) {       // round hid to tf32 so FFN2's A frags load raw
                o0.x = f2tf(fmaxf(o0.x, 0.f)); o0.y = f2tf(fmaxf(o0.y, 0.f));
                o1.x = f2tf(fmaxf(o1.x, 0.f)); o1.y = f2tf(fmaxf(o1.y, 0.f));
            }
            if (v0) *reinterpret_cast<float2*>(p0 + col) = o0;
            if (v1) *reinterpret_cast<float2*>(p1 + col) = o1;
        }
    }
}

// ---------------- combine pairs into output ----------------
__global__ void combine_kernel(float* __restrict__ out) {
    int i = blockIdx.x * blockDim.x + threadIdx.x;
    if (i >= T_TOKENS * (DD / 4)) return;
    int t  = i / (DD / 4);
    int d4 = i % (DD / 4);
    int r0 = g_row[t * 2 + 0];
    int r1 = g_row[t * 2 + 1];
    float g0 = g_gate[t * 2 + 0];
    float g1 = g_gate[t * 2 + 1];
    const float4* y0 = reinterpret_cast<const float4*>(g_y + (size_t)r0 * DD);
    const float4* y1 = reinterpret_cast<const float4*>(g_y + (size_t)r1 * DD);
    float4 a = y0[d4], b = y1[d4], o;
    o.x = g0 * a.x + g1 * b.x;
    o.y = g0 * a.y + g1 * b.y;
    o.z = g0 * a.z + g1 * b.z;
    o.w = g0 * a.w + g1 * b.w;
    reinterpret_cast<float4*>(out)[i] = o;
}

// ---------------- launch ----------------
extern "C" void kernel_launch(void* const* d_in, const int* in_sizes, int n_in,
                              void* d_out, int out_size) {
    const float* x  = (const float*)d_in[0];
    const float* wr = (const float*)d_in[1];
    const float* br = (const float*)d_in[2];
    const float* w1 = (const float*)d_in[3];
    const float* b1 = (const float*)d_in[4];
    const float* w2 = (const float*)d_in[5];
    const float* b2 = (const float*)d_in[6];
    float* out = (float*)d_out;

    cudaFuncSetAttribute(moe_gemm_mma<HH, DD, true>,
                         cudaFuncAttributeMaxDynamicSharedMemorySize, GEMM_SMEM);
    cudaFuncSetAttribute(moe_gemm_mma<DD, HH, false>,
                         cudaFuncAttributeMaxDynamicSharedMemorySize, GEMM_SMEM);

    // pre-round x to tf32 (33 MB; removes A-side cvts from FFN1 inner loop)
    round_x_kernel<<<1024, 256>>>((const float4*)x, (float4*)g_xr,
                                  T_TOKENS * DD / 4);

    zero_counts_kernel<<<1, 32>>>();
    router_kernel<<<T_TOKENS / 8, 256>>>(x, wr, br);
    offsets_kernel<<<1, 32>>>();
    scatter_kernel<<<PAIRS / 256, 256>>>();

    // FFN1: N=4096, K=1024  (weights read directly from harness buffer w1)
    {
        dim3 grid(HH / BN, 8192 / BM, EE);
        moe_gemm_mma<HH, DD, true><<<grid, 256, GEMM_SMEM>>>(g_xr, w1, b1);
    }
    // FFN2: N=1024, K=4096  (weights read directly from harness buffer w2)
    {
        dim3 grid(DD / BN, 8192 / BM, EE);
        moe_gemm_mma<DD, HH, false><<<grid, 256, GEMM_SMEM>>>(nullptr, w2, b2);
    }

    combine_kernel<<<(T_TOKENS * (DD / 4)) / 256, 256>>>(out);
}

// round 8
// speedup vs baseline: 26.6816x; 11.7998x over previous
#include <cuda_runtime.h>
#include <cuda_bf16.h>
#include <stdint.h>
#include <math.h>

// ---------------- problem constants ----------------
#define T_TOKENS 8192          // 4 * 2048
#define DD 1024                // emb dim
#define HH 4096                // hidden dim
#define EE 8                   // experts
#define PAIRS (T_TOKENS * 2)   // 16384 routed (token, expert) pairs

// ---------------- device scratch: EXACT R3 footprint (335 MB), nothing more ---
__device__ int   g_count[EE];
__device__ int   g_offset[EE];
__device__ int   g_ek[PAIRS];
__device__ int   g_slot[PAIRS];
__device__ float g_gate[PAIRS];
__device__ int   g_row[PAIRS];
__device__ int   g_tok[PAIRS];
__device__ float g_hid[(size_t)PAIRS * HH];     // 268 MB (tf32-rounded at write)
__device__ float g_y  [(size_t)PAIRS * DD];     // 67 MB; first 33 MB double as
                                                // tf32-rounded x before FFN2 runs

// ---------------- helpers ----------------
__device__ __forceinline__ uint32_t smem_u32(const void* p) {
    uint32_t a;
    asm("{ .reg .u64 t; cvta.to.shared.u64 t, %1; cvt.u32.u64 %0, t; }" : "=r"(a) : "l"(p));
    return a;
}
__device__ __forceinline__ void cp_async16(uint32_t dst, const void* src) {
    asm volatile("cp.async.cg.shared.global [%0], [%1], 16;" :: "r"(dst), "l"(src));
}
__device__ __forceinline__ void cp_commit() {
    asm volatile("cp.async.commit_group;" ::: "memory");
}
template <int N>
__device__ __forceinline__ void cp_wait() {
    asm volatile("cp.async.wait_group %0;" :: "n"(N) : "memory");
}
__device__ __forceinline__ float f2tf(float v) {
    uint32_t r;
    asm("cvt.rna.tf32.f32 %0, %1;" : "=r"(r) : "f"(v));
    return __uint_as_float(r);
}
__device__ __forceinline__ uint32_t f2tf_u(float v) {
    uint32_t r;
    asm("cvt.rna.tf32.f32 %0, %1;" : "=r"(r) : "f"(v));
    return r;
}
__device__ __forceinline__ void mma_tf32(float* d, const uint32_t* a, const uint32_t* b) {
    asm volatile(
        "mma.sync.aligned.m16n8k8.row.col.f32.tf32.tf32.f32 "
        "{%0,%1,%2,%3}, {%4,%5,%6,%7}, {%8,%9}, {%0,%1,%2,%3};"
        : "+f"(d[0]), "+f"(d[1]), "+f"(d[2]), "+f"(d[3])
        : "r"(a[0]), "r"(a[1]), "r"(a[2]), "r"(a[3]), "r"(b[0]), "r"(b[1]));
}

// ---------------- kernel: tf32 pre-round of x INTO g_y[0 : T*D] ----------------
__global__ void round_x_kernel(const float4* __restrict__ src, int n4) {
    float4* dst = reinterpret_cast<float4*>(g_y);
    int i = blockIdx.x * blockDim.x + threadIdx.x;
    int stride = gridDim.x * blockDim.x;
    for (; i < n4; i += stride) {
        float4 v = src[i];
        v.x = f2tf(v.x); v.y = f2tf(v.y); v.z = f2tf(v.z); v.w = f2tf(v.w);
        dst[i] = v;
    }
}

// ---------------- kernel 0: zero counters ----------------
__global__ void zero_counts_kernel() {
    if (threadIdx.x < EE) g_count[threadIdx.x] = 0;
}

// ---------------- kernel 1: router (1 warp per token, fp32, ORIGINAL x) ------
__global__ void router_kernel(const float* __restrict__ x,
                              const float* __restrict__ wr,
                              const float* __restrict__ br) {
    int warp = (blockIdx.x * blockDim.x + threadIdx.x) >> 5;
    int lane = threadIdx.x & 31;
    if (warp >= T_TOKENS) return;
    const float* xr = x + (size_t)warp * DD;

    float acc[EE];
#pragma unroll
    for (int e = 0; e < EE; e++) acc[e] = 0.f;
#pragma unroll 4
    for (int c = 0; c < DD / 32; c++) {
        int k = c * 32 + lane;
        float xv = __ldg(xr + k);
        const float4* w4 = reinterpret_cast<const float4*>(wr + (size_t)k * EE);
        float4 a = __ldg(&w4[0]);
        float4 b = __ldg(&w4[1]);
        acc[0] += xv * a.x; acc[1] += xv * a.y; acc[2] += xv * a.z; acc[3] += xv * a.w;
        acc[4] += xv * b.x; acc[5] += xv * b.y; acc[6] += xv * b.z; acc[7] += xv * b.w;
    }
#pragma unroll
    for (int e = 0; e < EE; e++)
#pragma unroll
        for (int o = 16; o > 0; o >>= 1)
            acc[e] += __shfl_down_sync(0xffffffffu, acc[e], o);

    if (lane == 0) {
        float l[EE];
        float mx = -1e30f;
#pragma unroll
        for (int e = 0; e < EE; e++) { l[e] = acc[e] + br[e]; mx = fmaxf(mx, l[e]); }
        float s = 0.f;
#pragma unroll
        for (int e = 0; e < EE; e++) { l[e] = expf(l[e] - mx); s += l[e]; }
        float inv = 1.0f / s;
        int e0 = 0;
#pragma unroll
        for (int e = 1; e < EE; e++) if (l[e] > l[e0]) e0 = e;
        int e1 = (e0 == 0) ? 1 : 0;
#pragma unroll
        for (int e = 0; e < EE; e++) if (e != e0 && l[e] > l[e1]) e1 = e;
        int t = warp;
        int s0 = atomicAdd(&g_count[e0], 1);
        g_ek[t * 2 + 0] = e0; g_slot[t * 2 + 0] = s0; g_gate[t * 2 + 0] = l[e0] * inv;
        int s1 = atomicAdd(&g_count[e1], 1);
        g_ek[t * 2 + 1] = e1; g_slot[t * 2 + 1] = s1; g_gate[t * 2 + 1] = l[e1] * inv;
    }
}

// ---------------- kernel 2: prefix offsets ----------------
__global__ void offsets_kernel() {
    if (threadIdx.x == 0 && blockIdx.x == 0) {
        int s = 0;
#pragma unroll
        for (int e = 0; e < EE; e++) { g_offset[e] = s; s += g_count[e]; }
    }
}

// ---------------- kernel 3: scatter compact rows ----------------
__global__ void scatter_kernel() {
    int i = blockIdx.x * blockDim.x + threadIdx.x;
    if (i >= PAIRS) return;
    int e = g_ek[i];
    int row = g_offset[e] + g_slot[i];
    g_row[i] = row;
    g_tok[row] = i >> 1;
}

// ---------------- grouped GEMM via mma.sync tf32 (R3 shape) ----------------
// C[m][n] = sum_k A[m][k] * W[k][n]  (+bias; FFN1 adds relu + tf32-round)
// FFN1: A = g_y[token] (tf32-rounded x, aliased) -> raw frag loads
// FFN2: A = g_hid[row] (tf32-rounded at FFN1 epilogue) -> raw frag loads
// B (harness weight buffers) converts in-loop.
constexpr int BM = 128, BN = 128, BK = 32;
constexpr int A_STRIDE = BK + 4;             // 36 floats
constexpr int B_STRIDE = BN + 8;             // 136 floats
constexpr int A_TILE_F = BM * A_STRIDE;      // 4608 floats
constexpr int B_TILE_F = BK * B_STRIDE;      // 4352 floats
constexpr int STAGE_F  = A_TILE_F + B_TILE_F;
constexpr int GEMM_SMEM = 2 * STAGE_F * 4;   // 71680 bytes

template <int NN, int KK, bool FFN1>
__global__ void __launch_bounds__(256, 2)
moe_gemm_mma(const float* __restrict__ W_all,
             const float* __restrict__ bias_all) {
    constexpr int NCH = KK / BK;
    extern __shared__ float sm[];

    int e = blockIdx.z;
    int cnt = g_count[e];
    int m0 = blockIdx.y * BM;
    if (m0 >= cnt) return;
    int off = g_offset[e];
    int n0 = blockIdx.x * BN;

    const float* W    = W_all + (size_t)e * KK * NN;
    const float* bias = bias_all + (size_t)e * NN;
    float* C          = FFN1 ? g_hid : g_y;

    int tid = threadIdx.x;
    int wid = tid >> 5, lane = tid & 31;
    int wm = wid >> 2, wn = wid & 3;        // 2 x 4 warps; warp tile 64(m) x 32(n)
    int g = lane >> 2, tg = lane & 3;

    uint32_t sb = smem_u32(sm);

    // ---- per-thread load descriptors (R3 layout) ----
    const float* asrc[4];
    uint32_t adst[4];
    int aseg = tid & 7;
#pragma unroll
    for (int i = 0; i < 4; i++) {
        int r = i * 32 + (tid >> 3);
        int gm = m0 + r;
        if (gm > cnt - 1) gm = cnt - 1;     // clamp; masked in epilogue
        int grow = off + gm;
        const float* base = FFN1 ? (g_y + (size_t)g_tok[grow] * KK)    // aliased tf32 x
                                 : (g_hid + (size_t)grow * KK);
        asrc[i] = base + aseg * 4;
        adst[i] = sb + (uint32_t)(r * A_STRIDE + aseg * 4) * 4;
    }
    const float* bsrc[4];
    uint32_t bdst[4];
    int bseg = tid & 31;
#pragma unroll
    for (int i = 0; i < 4; i++) {
        int kr = i * 8 + (tid >> 5);
        bsrc[i] = W + (size_t)kr * NN + n0 + bseg * 4;
        bdst[i] = sb + (uint32_t)(A_TILE_F + kr * B_STRIDE + bseg * 4) * 4;
    }
    constexpr uint32_t STAGE_B = STAGE_F * 4;

    float acc[4][4][4];
#pragma unroll
    for (int mi = 0; mi < 4; mi++)
#pragma unroll
        for (int ni = 0; ni < 4; ni++)
#pragma unroll
            for (int q = 0; q < 4; q++) acc[mi][ni][q] = 0.f;

    // ---- prologue: stage 0 ----
#pragma unroll
    for (int i = 0; i < 4; i++) cp_async16(adst[i], asrc[i]);
#pragma unroll
    for (int i = 0; i < 4; i++) cp_async16(bdst[i], bsrc[i]);
    cp_commit();

#pragma unroll 1
    for (int c = 0; c < NCH; c++) {
        if (c + 1 < NCH) {
            int k0 = (c + 1) * BK;
            uint32_t so = ((c + 1) & 1) * STAGE_B;
#pragma unroll
            for (int i = 0; i < 4; i++) cp_async16(adst[i] + so, asrc[i] + k0);
#pragma unroll
            for (int i = 0; i < 4; i++)
                cp_async16(bdst[i] + so, bsrc[i] + (size_t)k0 * NN);
            cp_commit();
            cp_wait<1>();
        } else {
            cp_wait<0>();
        }
        __syncthreads();

        const uint32_t* As = reinterpret_cast<const uint32_t*>(sm) + (c & 1) * STAGE_F;
        const float*    Bs = sm + (c & 1) * STAGE_F + A_TILE_F;

#pragma unroll
        for (int kk = 0; kk < BK; kk += 8) {
            uint32_t af[4][4], bf[4][2];
#pragma unroll
            for (int mi = 0; mi < 4; mi++) {
                const uint32_t* ap = As + (wm * 64 + mi * 16 + g) * A_STRIDE + kk + tg;
                af[mi][0] = ap[0];                      // pre-rounded: raw load
                af[mi][1] = ap[8 * A_STRIDE];
                af[mi][2] = ap[4];
                af[mi][3] = ap[8 * A_STRIDE + 4];
            }
#pragma unroll
            for (int ni = 0; ni < 4; ni++) {
                const float* bp = Bs + (kk + tg) * B_STRIDE + wn * 32 + ni * 8 + g;
                bf[ni][0] = f2tf_u(bp[0]);              // raw weights: cvt here
                bf[ni][1] = f2tf_u(bp[4 * B_STRIDE]);
            }
#pragma unroll
            for (int mi = 0; mi < 4; mi++)
#pragma unroll
                for (int ni = 0; ni < 4; ni++)
                    mma_tf32(acc[mi][ni], af[mi], bf[ni]);
        }
        __syncthreads();
    }

    // ---- epilogue: bias (+relu + tf32 round for FFN1), masked float2 stores ----
#pragma unroll
    for (int mi = 0; mi < 4; mi++) {
        int r0 = m0 + wm * 64 + mi * 16 + g;
        int r1 = r0 + 8;
        bool v0 = r0 < cnt, v1 = r1 < cnt;
        float* p0 = C + (size_t)(off + r0) * NN + n0 + wn * 32;
        float* p1 = C + (size_t)(off + r1) * NN + n0 + wn * 32;
#pragma unroll
        for (int ni = 0; ni < 4; ni++) {
            int col = ni * 8 + 2 * tg;
            float2 bv = *reinterpret_cast<const float2*>(bias + n0 + wn * 32 + col);
            float2 o0, o1;
            o0.x = acc[mi][ni][0] + bv.x;
            o0.y = acc[mi][ni][1] + bv.y;
            o1.x = acc[mi][ni][2] + bv.x;
            o1.y = acc[mi][ni][3] + bv.y;
            if (FFN1) {       // round hid to tf32 so FFN2's A frags load raw
                o0.x = f2tf(fmaxf(o0.x, 0.f)); o0.y = f2tf(fmaxf(o0.y, 0.f));
                o1.x = f2tf(fmaxf(o1.x, 0.f)); o1.y = f2tf(fmaxf(o1.y, 0.f));
            }
            if (v0) *reinterpret_cast<float2*>(p0 + col) = o0;
            if (v1) *reinterpret_cast<float2*>(p1 + col) = o1;
        }
    }
}

// ---------------- combine pairs into output ----------------
__global__ void combine_kernel(float* __restrict__ out) {
    int i = blockIdx.x * blockDim.x + threadIdx.x;
    if (i >= T_TOKENS * (DD / 4)) return;
    int t  = i / (DD / 4);
    int d4 = i % (DD / 4);
    int r0 = g_row[t * 2 + 0];
    int r1 = g_row[t * 2 + 1];
    float g0 = g_gate[t * 2 + 0];
    float g1 = g_gate[t * 2 + 1];
    const float4* y0 = reinterpret_cast<const float4*>(g_y + (size_t)r0 * DD);
    const float4* y1 = reinterpret_cast<const float4*>(g_y + (size_t)r1 * DD);
    float4 a = y0[d4], b = y1[d4], o;
    o.x = g0 * a.x + g1 * b.x;
    o.y = g0 * a.y + g1 * b.y;
    o.z = g0 * a.z + g1 * b.z;
    o.w = g0 * a.w + g1 * b.w;
    reinterpret_cast<float4*>(out)[i] = o;
}

// ---------------- launch ----------------
extern "C" void kernel_launch(void* const* d_in, const int* in_sizes, int n_in,
                              void* d_out, int out_size) {
    const float* x  = (const float*)d_in[0];
    const float* wr = (const float*)d_in[1];
    const float* br = (const float*)d_in[2];
    const float* w1 = (const float*)d_in[3];
    const float* b1 = (const float*)d_in[4];
    const float* w2 = (const float*)d_in[5];
    const float* b2 = (const float*)d_in[6];
    float* out = (float*)d_out;

    cudaFuncSetAttribute(moe_gemm_mma<HH, DD, true>,
                         cudaFuncAttributeMaxDynamicSharedMemorySize, GEMM_SMEM);
    cudaFuncSetAttribute(moe_gemm_mma<DD, HH, false>,
                         cudaFuncAttributeMaxDynamicSharedMemorySize, GEMM_SMEM);

    // round x -> tf32 into g_y's first 33 MB (dead until FFN2 overwrites it)
    round_x_kernel<<<1024, 256>>>((const float4*)x, T_TOKENS * DD / 4);

    zero_counts_kernel<<<1, 32>>>();
    router_kernel<<<T_TOKENS / 8, 256>>>(x, wr, br);
    offsets_kernel<<<1, 32>>>();
    scatter_kernel<<<PAIRS / 256, 256>>>();

    // FFN1: N=4096, K=1024  (A from aliased g_y; weights from harness buffer)
    {
        dim3 grid(HH / BN, 8192 / BM, EE);
        moe_gemm_mma<HH, DD, true><<<grid, 256, GEMM_SMEM>>>(w1, b1);
    }
    // FFN2: N=1024, K=4096  (A from g_hid; overwrites g_y)
    {
        dim3 grid(DD / BN, 8192 / BM, EE);
        moe_gemm_mma<DD, HH, false><<<grid, 256, GEMM_SMEM>>>(w2, b2);
    }

    combine_kernel<<<(T_TOKENS * (DD / 4)) / 256, 256>>>(out);
}